// round 3
// baseline (speedup 1.0000x reference)
#include <cuda_runtime.h>
#include <cstdint>
#include <cstddef>

#define IN_F   8192
#define OUT_F  8192
#define BATCH  32
#define KSPLIT 8
#define KCHUNK (IN_F / KSPLIT)      // 1024
#define TK     128                  // x tile depth (16 KB smem)
#define ROWS_PER_BLOCK 256
#define THREADS_GEMM   128          // 4 warps, each warp covers 64 rows (2 per lane)

// Scratch (no allocations allowed): transposed x and k-split partials.
__device__ float g_xt[(size_t)IN_F * BATCH];                    // 1 MB
__device__ float g_partial[(size_t)KSPLIT * OUT_F * BATCH];     // 8 MB

// ---- Blackwell packed f32x2 helpers ----------------------------------------
__device__ __forceinline__ unsigned long long fma2(unsigned long long a,
                                                   unsigned long long b,
                                                   unsigned long long c) {
    unsigned long long d;
    asm("fma.rn.f32x2 %0, %1, %2, %3;" : "=l"(d) : "l"(a), "l"(b), "l"(c));
    return d;
}
__device__ __forceinline__ unsigned long long dup2(float f) {
    unsigned long long r;
    asm("mov.b64 %0, {%1, %1};" : "=l"(r) : "f"(f));
    return r;
}

// ---- Kernel 1: transpose x [B, IN] -> xt [IN, B] ----------------------------
// Makes batch the fastest-varying dim so batch-pairs are contiguous 8B words.
__global__ void xt_kernel(const float* __restrict__ x) {
    int g = blockIdx.x * blockDim.x + threadIdx.x;   // 262144 threads
    int i = g >> 5;
    int b = g & 31;
    g_xt[g] = x[(size_t)b * IN_F + i];               // writes coalesced; x stays L2-hot
}

// ---- Kernel 2: main ternary GEMM --------------------------------------------
// grid = (OUT_F/ROWS_PER_BLOCK, KSPLIT) = (32, 8). Each lane owns rows r0, r0+32
// with 32 f32 accumulators each (16 f32x2). All 4 warps share the same k range,
// so the x tile in smem is read as pure broadcast LDS.128 (conflict-free).
__global__ void __launch_bounds__(THREADS_GEMM, 4)
gemm_kernel(const int* __restrict__ W) {
    __shared__ float sx[TK * BATCH];                 // 16 KB

    const int tid     = threadIdx.x;
    const int lane    = tid & 31;
    const int warp    = tid >> 5;
    const int rowbase = blockIdx.x * ROWS_PER_BLOCK;
    const int kbase   = blockIdx.y * KCHUNK;
    const int r0      = rowbase + warp * 64 + lane;
    const int r1      = r0 + 32;

    unsigned long long acc0[16], acc1[16];
#pragma unroll
    for (int p = 0; p < 16; p++) { acc0[p] = 0ULL; acc1[p] = 0ULL; }

    const int4* __restrict__ w0p = (const int4*)(W + (size_t)r0 * IN_F + kbase);
    const int4* __restrict__ w1p = (const int4*)(W + (size_t)r1 * IN_F + kbase);

    for (int kt = 0; kt < KCHUNK; kt += TK) {
        __syncthreads();
        // Stage x tile: region is contiguous in g_xt ([k][b] layout) -> coalesced copy.
        {
            const float4* src = (const float4*)(g_xt + (size_t)(kbase + kt) * BATCH);
            float4* dst = (float4*)sx;
#pragma unroll
            for (int j = tid; j < TK * BATCH / 4; j += THREADS_GEMM)
                dst[j] = src[j];
        }
        __syncthreads();

#pragma unroll 1
        for (int kk = 0; kk < TK; kk += 4) {
            const int idx = (kt + kk) >> 2;
            int4 wa = w0p[idx];                      // 4 weights for row r0 (L1-streamed)
            int4 wb = w1p[idx];                      // 4 weights for row r1

            unsigned long long d0[4], d1[4];
            d0[0] = dup2((float)wa.x); d0[1] = dup2((float)wa.y);
            d0[2] = dup2((float)wa.z); d0[3] = dup2((float)wa.w);
            d1[0] = dup2((float)wb.x); d1[1] = dup2((float)wb.y);
            d1[2] = dup2((float)wb.z); d1[3] = dup2((float)wb.w);

#pragma unroll
            for (int q = 0; q < 4; q++) {
                const ulonglong2* xp = (const ulonglong2*)(sx + (kk + q) * BATCH);
#pragma unroll
                for (int p = 0; p < 8; p++) {
                    ulonglong2 xv = xp[p];           // broadcast LDS.128: 4 batch values
                    acc0[2*p]   = fma2(d0[q], xv.x, acc0[2*p]);
                    acc0[2*p+1] = fma2(d0[q], xv.y, acc0[2*p+1]);
                    acc1[2*p]   = fma2(d1[q], xv.x, acc1[2*p]);
                    acc1[2*p+1] = fma2(d1[q], xv.y, acc1[2*p+1]);
                }
            }
        }
    }

    // Write k-split partials: partial[ky][row][b], 128B-aligned rows.
    unsigned long long* o0 =
        (unsigned long long*)(g_partial + ((size_t)blockIdx.y * OUT_F + r0) * BATCH);
    unsigned long long* o1 =
        (unsigned long long*)(g_partial + ((size_t)blockIdx.y * OUT_F + r1) * BATCH);
#pragma unroll
    for (int p = 0; p < 16; p++) { o0[p] = acc0[p]; o1[p] = acc1[p]; }
}

// ---- Kernel 3: reduce k-splits, apply softplus scale + bias -----------------
// 65536 threads; thread g owns (o = g>>3, batch quad bq = g&7). Reads coalesced.
__global__ void reduce_kernel(const float* __restrict__ log_scale,
                              const float* __restrict__ bias,
                              float* __restrict__ out) {
    int g  = blockIdx.x * blockDim.x + threadIdx.x;
    int o  = g >> 3;
    int bq = g & 7;

    const float4* base = (const float4*)g_partial;
    float4 s = make_float4(0.f, 0.f, 0.f, 0.f);
#pragma unroll
    for (int ky = 0; ky < KSPLIT; ky++) {
        float4 p = base[((size_t)ky * OUT_F + o) * (BATCH / 4) + bq];
        s.x += p.x; s.y += p.y; s.z += p.z; s.w += p.w;
    }

    float ls = log_scale[o];
    float sp = (ls > 20.0f) ? ls : log1pf(expf(ls));   // softplus, overflow-safe
    float sc = fmaxf(sp, 1e-4f);
    float bi = bias[o];

    int b0 = bq << 2;
    out[(size_t)(b0 + 0) * OUT_F + o] = fmaf(sc, s.x, bi);
    out[(size_t)(b0 + 1) * OUT_F + o] = fmaf(sc, s.y, bi);
    out[(size_t)(b0 + 2) * OUT_F + o] = fmaf(sc, s.z, bi);
    out[(size_t)(b0 + 3) * OUT_F + o] = fmaf(sc, s.w, bi);
}

// ---- Launch ------------------------------------------------------------------
extern "C" void kernel_launch(void* const* d_in, const int* in_sizes, int n_in,
                              void* d_out, int out_size) {
    // Robust input mapping by size: x = B*IN, W = OUT*IN; log_scale then bias
    // keep their metadata order among the two length-8192 vectors.
    const float* x  = nullptr;
    const int*   W  = nullptr;
    const float* ls = nullptr;
    const float* bi = nullptr;
    for (int i = 0; i < n_in; i++) {
        long long sz = in_sizes[i];
        if (sz == (long long)OUT_F * IN_F)      W = (const int*)d_in[i];
        else if (sz == (long long)BATCH * IN_F) x = (const float*)d_in[i];
        else if (sz == OUT_F) {
            if (!ls) ls = (const float*)d_in[i];
            else     bi = (const float*)d_in[i];
        }
    }
    float* out = (float*)d_out;

    xt_kernel<<<(IN_F * BATCH) / 256, 256>>>(x);

    dim3 grid(OUT_F / ROWS_PER_BLOCK, KSPLIT);   // (32, 8) = 256 blocks
    gemm_kernel<<<grid, THREADS_GEMM>>>(W);

    reduce_kernel<<<(OUT_F * BATCH / 4) / 256, 256>>>(ls, bi, out);
}

// round 4
// speedup vs baseline: 1.1202x; 1.1202x over previous
#include <cuda_runtime.h>
#include <cstdint>
#include <cstddef>

#define IN_F   8192
#define OUT_F  8192
#define BATCH  32
#define KSPLIT 32
#define KCHUNK (IN_F / KSPLIT)      // 256
#define ROWS_PER_BLOCK 256
#define THREADS_GEMM   128          // 4 warps; warp covers 64 rows (2 per lane)

// Scratch (no allocations allowed): transposed x and k-split partials.
__device__ float g_xt[(size_t)IN_F * BATCH];                    // 1 MB
__device__ float g_partial[(size_t)KSPLIT * OUT_F * BATCH];     // 33.5 MB

// ---- Blackwell packed f32x2 helpers ----------------------------------------
__device__ __forceinline__ unsigned long long fma2(unsigned long long a,
                                                   unsigned long long b,
                                                   unsigned long long c) {
    unsigned long long d;
    asm("fma.rn.f32x2 %0, %1, %2, %3;" : "=l"(d) : "l"(a), "l"(b), "l"(c));
    return d;
}
__device__ __forceinline__ unsigned long long dup2(float f) {
    unsigned long long r;
    asm("mov.b64 %0, {%1, %1};" : "=l"(r) : "f"(f));
    return r;
}

// ---- Kernel 1: transpose x [B, IN] -> xt [IN, B], both sides coalesced ------
__global__ void xt_kernel(const float* __restrict__ x) {
    __shared__ float t[32][33];
    const int tx = threadIdx.x;        // 32
    const int ty = threadIdx.y;        // 8
    const int i0 = blockIdx.x * 32;    // gridDim.x = IN_F/32 = 256
#pragma unroll
    for (int s = 0; s < 4; s++) {
        int b = ty + 8 * s;
        t[b][tx] = x[(size_t)b * IN_F + i0 + tx];      // coalesced over i
    }
    __syncthreads();
#pragma unroll
    for (int s = 0; s < 4; s++) {
        int r = ty + 8 * s;
        g_xt[(size_t)(i0 + r) * BATCH + tx] = t[tx][r]; // coalesced over b
    }
}

// ---- Kernel 2: main ternary GEMM --------------------------------------------
// grid = (OUT_F/ROWS_PER_BLOCK, KSPLIT) = (32, 32) = 1024 blocks.
// Each lane owns rows r0, r0+32 with 32 batch accumulators each (16 f32x2).
// x tile (KCHUNK x 32 = 32 KB) staged once; weights prefetched one iter ahead.
__global__ void __launch_bounds__(THREADS_GEMM, 4)
gemm_kernel(const int* __restrict__ W) {
    __shared__ float sx[KCHUNK * BATCH];                 // 32 KB

    const int tid     = threadIdx.x;
    const int lane    = tid & 31;
    const int warp    = tid >> 5;
    const int rowbase = blockIdx.x * ROWS_PER_BLOCK;
    const int kbase   = blockIdx.y * KCHUNK;
    const int r0      = rowbase + warp * 64 + lane;
    const int r1      = r0 + 32;

    // Stage the whole x tile once (contiguous in g_xt -> coalesced).
    {
        const float4* __restrict__ src =
            (const float4*)(g_xt + (size_t)kbase * BATCH);
        float4* dst = (float4*)sx;
#pragma unroll
        for (int j = tid; j < KCHUNK * BATCH / 4; j += THREADS_GEMM)
            dst[j] = src[j];
    }

    unsigned long long acc0[16], acc1[16];
#pragma unroll
    for (int p = 0; p < 16; p++) { acc0[p] = 0ULL; acc1[p] = 0ULL; }

    const int4* __restrict__ w0p = (const int4*)(W + (size_t)r0 * IN_F + kbase);
    const int4* __restrict__ w1p = (const int4*)(W + (size_t)r1 * IN_F + kbase);

    __syncthreads();

    const int NIT = KCHUNK / 4;                          // 64
    int4 wa = w0p[0];
    int4 wb = w1p[0];

#pragma unroll 1
    for (int it = 0; it < NIT; ++it) {
        // Prefetch next iteration's weights before the long FFMA2 body.
        const int nid = (it + 1 < NIT) ? it + 1 : it;
        int4 na = w0p[nid];
        int4 nb = w1p[nid];

        unsigned long long d0[4], d1[4];
        d0[0] = dup2((float)wa.x); d0[1] = dup2((float)wa.y);
        d0[2] = dup2((float)wa.z); d0[3] = dup2((float)wa.w);
        d1[0] = dup2((float)wb.x); d1[1] = dup2((float)wb.y);
        d1[2] = dup2((float)wb.z); d1[3] = dup2((float)wb.w);

        const float* xk = sx + (size_t)it * 4 * BATCH;
#pragma unroll
        for (int q = 0; q < 4; q++) {
            const ulonglong2* __restrict__ xp =
                (const ulonglong2*)(xk + q * BATCH);
#pragma unroll
            for (int p = 0; p < 8; p++) {
                ulonglong2 xv = xp[p];                   // broadcast LDS.128
                acc0[2*p]   = fma2(d0[q], xv.x, acc0[2*p]);
                acc0[2*p+1] = fma2(d0[q], xv.y, acc0[2*p+1]);
                acc1[2*p]   = fma2(d1[q], xv.x, acc1[2*p]);
                acc1[2*p+1] = fma2(d1[q], xv.y, acc1[2*p+1]);
            }
        }
        wa = na; wb = nb;
    }

    // Write k-split partials: partial[ky][row][b].
    unsigned long long* o0 =
        (unsigned long long*)(g_partial + ((size_t)blockIdx.y * OUT_F + r0) * BATCH);
    unsigned long long* o1 =
        (unsigned long long*)(g_partial + ((size_t)blockIdx.y * OUT_F + r1) * BATCH);
#pragma unroll
    for (int p = 0; p < 16; p++) { o0[p] = acc0[p]; o1[p] = acc1[p]; }
}

// ---- Kernel 3: reduce k-splits, apply softplus scale + bias -----------------
__global__ void reduce_kernel(const float* __restrict__ log_scale,
                              const float* __restrict__ bias,
                              float* __restrict__ out) {
    int g  = blockIdx.x * blockDim.x + threadIdx.x;
    int o  = g >> 3;
    int bq = g & 7;

    const float4* __restrict__ base = (const float4*)g_partial;
    float4 s = make_float4(0.f, 0.f, 0.f, 0.f);
#pragma unroll
    for (int ky = 0; ky < KSPLIT; ky++) {
        float4 p = base[((size_t)ky * OUT_F + o) * (BATCH / 4) + bq];
        s.x += p.x; s.y += p.y; s.z += p.z; s.w += p.w;
    }

    float ls = log_scale[o];
    float sp = (ls > 20.0f) ? ls : log1pf(expf(ls));   // softplus, overflow-safe
    float sc = fmaxf(sp, 1e-4f);
    float bi = bias[o];

    int b0 = bq << 2;
    out[(size_t)(b0 + 0) * OUT_F + o] = fmaf(sc, s.x, bi);
    out[(size_t)(b0 + 1) * OUT_F + o] = fmaf(sc, s.y, bi);
    out[(size_t)(b0 + 2) * OUT_F + o] = fmaf(sc, s.z, bi);
    out[(size_t)(b0 + 3) * OUT_F + o] = fmaf(sc, s.w, bi);
}

// ---- Launch ------------------------------------------------------------------
extern "C" void kernel_launch(void* const* d_in, const int* in_sizes, int n_in,
                              void* d_out, int out_size) {
    const float* x  = nullptr;
    const int*   W  = nullptr;
    const float* ls = nullptr;
    const float* bi = nullptr;
    for (int i = 0; i < n_in; i++) {
        long long sz = in_sizes[i];
        if (sz == (long long)OUT_F * IN_F)      W = (const int*)d_in[i];
        else if (sz == (long long)BATCH * IN_F) x = (const float*)d_in[i];
        else if (sz == OUT_F) {
            if (!ls) ls = (const float*)d_in[i];
            else     bi = (const float*)d_in[i];
        }
    }
    float* out = (float*)d_out;

    dim3 tb(32, 8);
    xt_kernel<<<IN_F / 32, tb>>>(x);

    dim3 grid(OUT_F / ROWS_PER_BLOCK, KSPLIT);   // (32, 32) = 1024 blocks
    gemm_kernel<<<grid, THREADS_GEMM>>>(W);

    reduce_kernel<<<(OUT_F * BATCH / 4) / 256, 256>>>(ls, bi, out);
}

// round 6
// speedup vs baseline: 1.4765x; 1.3181x over previous
#include <cuda_runtime.h>
#include <cuda_bf16.h>
#include <cstdint>
#include <cstddef>

#define IN_F   8192
#define OUT_F  8192
#define BATCH  32
#define KSPLIT 4
#define KCHUNK (IN_F / KSPLIT)     // 2048
#define NIT    (KCHUNK / 16)       // 128 k16 steps
#define MTILE  128                 // rows per CTA (4 warps x 32 rows)
#define THREADS 128

// Scratch: bf16 hi/lo stacked activations [n][k] (n<32 hi, n>=32 lo), partials.
__device__ __nv_bfloat16 g_xbf[(size_t)64 * IN_F];               // 1 MB
__device__ float g_partial[(size_t)KSPLIT * OUT_F * BATCH];      // 4 MB

// ---- helpers -----------------------------------------------------------------
__device__ __forceinline__ uint32_t pack_bf16x2(int lo, int hi) {
    // exact for ternary {-1,0,1}; lo -> low half, hi -> high half
    float fl = (float)lo, fh = (float)hi;
    uint32_t r;
    asm("cvt.rn.bf16x2.f32 %0, %1, %2;" : "=r"(r) : "f"(fh), "f"(fl));
    return r;
}

__device__ __forceinline__ void mma16816(float* d, uint32_t a0, uint32_t a1,
                                         uint32_t a2, uint32_t a3,
                                         uint32_t b0, uint32_t b1) {
    asm volatile(
        "mma.sync.aligned.m16n8k16.row.col.f32.bf16.bf16.f32 "
        "{%0,%1,%2,%3}, {%4,%5,%6,%7}, {%8,%9}, {%0,%1,%2,%3};"
        : "+f"(d[0]), "+f"(d[1]), "+f"(d[2]), "+f"(d[3])
        : "r"(a0), "r"(a1), "r"(a2), "r"(a3), "r"(b0), "r"(b1));
}

// ---- Kernel 1: x[32][8192] f32 -> g_xbf hi rows 0..31, lo rows 32..63 -------
__global__ void xprep_kernel(const float* __restrict__ x) {
    int g  = blockIdx.x * blockDim.x + threadIdx.x;   // 65536 threads
    int b  = g >> 11;
    int k4 = g & 2047;
    float4 v = ((const float4*)(x + (size_t)b * IN_F))[k4];

    __nv_bfloat162 hA = __floats2bfloat162_rn(v.x, v.y);
    __nv_bfloat162 hB = __floats2bfloat162_rn(v.z, v.w);
    float lx = v.x - __bfloat162float(hA.x);
    float ly = v.y - __bfloat162float(hA.y);
    float lz = v.z - __bfloat162float(hB.x);
    float lw = v.w - __bfloat162float(hB.y);
    __nv_bfloat162 lA = __floats2bfloat162_rn(lx, ly);
    __nv_bfloat162 lB = __floats2bfloat162_rn(lz, lw);

    __nv_bfloat162* hi = (__nv_bfloat162*)(g_xbf + (size_t)b * IN_F + k4 * 4);
    __nv_bfloat162* lo = (__nv_bfloat162*)(g_xbf + (size_t)(b + 32) * IN_F + k4 * 4);
    hi[0] = hA; hi[1] = hB;
    lo[0] = lA; lo[1] = lB;
}

// ---- Kernel 2: smem-free HMMA GEMM -------------------------------------------
// grid=(OUT_F/MTILE, KSPLIT)=(64,4). Warp w owns rows rowbase+w*32..+31, N=64.
// A fragments LDG'd straight from W (int32) and cvt'd to bf16; B fragments are
// single 32-bit loads from g_xbf (L1/L2-hot). Next-iteration A prefetched.
__global__ void __launch_bounds__(THREADS, 3)
gemm_kernel(const int* __restrict__ W) {
    const int tid  = threadIdx.x;
    const int lane = tid & 31;
    const int warp = tid >> 5;
    const int g    = lane >> 2;        // fragment group id (0..7)
    const int t    = lane & 3;         // thread-in-group (0..3)

    const int rowbase = blockIdx.x * MTILE + warp * 32;
    const int kbase   = blockIdx.y * KCHUNK;

    // Row base pointers for the 4 fragment rows (2 m-tiles x {g, g+8}).
    const int* __restrict__ p00 = W + (size_t)(rowbase + g     ) * IN_F + kbase + 2 * t;
    const int* __restrict__ p01 = W + (size_t)(rowbase + g +  8) * IN_F + kbase + 2 * t;
    const int* __restrict__ p10 = W + (size_t)(rowbase + g + 16) * IN_F + kbase + 2 * t;
    const int* __restrict__ p11 = W + (size_t)(rowbase + g + 24) * IN_F + kbase + 2 * t;

    // B pointers: n = g + 8j, k contiguous.
    const __nv_bfloat16* __restrict__ xb = g_xbf + kbase + 2 * t;

    float acc[2][8][4];
#pragma unroll
    for (int mt = 0; mt < 2; mt++)
#pragma unroll
        for (int j = 0; j < 8; j++)
#pragma unroll
            for (int e = 0; e < 4; e++) acc[mt][j][e] = 0.f;

    // A registers: [mtile*4 + frag] ; frag: 0=(g,k) 1=(g+8,k) 2=(g,k+8) 3=(g+8,k+8)
    int2 ca[8], na[8];

#define LOAD_A(dst, ko)                                              \
    do {                                                             \
        dst[0] = *(const int2*)(p00 + (ko));                         \
        dst[1] = *(const int2*)(p01 + (ko));                         \
        dst[2] = *(const int2*)(p00 + (ko) + 8);                     \
        dst[3] = *(const int2*)(p01 + (ko) + 8);                     \
        dst[4] = *(const int2*)(p10 + (ko));                         \
        dst[5] = *(const int2*)(p11 + (ko));                         \
        dst[6] = *(const int2*)(p10 + (ko) + 8);                     \
        dst[7] = *(const int2*)(p11 + (ko) + 8);                     \
    } while (0)

    LOAD_A(ca, 0);

#pragma unroll 2
    for (int it = 0; it < NIT; ++it) {
        const int ko = it * 16;

        // B fragments for this k16 (16x 32-bit loads, L1-hot).
        uint32_t b0[8], b1[8];
#pragma unroll
        for (int j = 0; j < 8; j++) {
            const __nv_bfloat16* pb = xb + (size_t)(g + 8 * j) * IN_F + ko;
            b0[j] = *(const uint32_t*)(pb);
            b1[j] = *(const uint32_t*)(pb + 8);
        }

        // Prefetch next iteration's A while we convert + mma the current one.
        if (it + 1 < NIT) LOAD_A(na, ko + 16);

        uint32_t A[8];
#pragma unroll
        for (int q = 0; q < 8; q++) A[q] = pack_bf16x2(ca[q].x, ca[q].y);

#pragma unroll
        for (int j = 0; j < 8; j++) {
            mma16816(acc[0][j], A[0], A[1], A[2], A[3], b0[j], b1[j]);
            mma16816(acc[1][j], A[4], A[5], A[6], A[7], b0[j], b1[j]);
        }

#pragma unroll
        for (int q = 0; q < 8; q++) ca[q] = na[q];
    }

    // Epilogue: combine hi (j<4) + lo (j+4), store f32 partials.
    // D fragment: d0=D[g][2t], d1=D[g][2t+1], d2=D[g+8][2t], d3=D[g+8][2t+1]
    float* pk = g_partial + (size_t)blockIdx.y * OUT_F * BATCH;
#pragma unroll
    for (int mt = 0; mt < 2; mt++) {
        const int r0 = rowbase + mt * 16 + g;
#pragma unroll
        for (int j = 0; j < 4; j++) {
            const int n0 = 8 * j + 2 * t;
            float2 v0, v1;
            v0.x = acc[mt][j][0] + acc[mt][j + 4][0];
            v0.y = acc[mt][j][1] + acc[mt][j + 4][1];
            v1.x = acc[mt][j][2] + acc[mt][j + 4][2];
            v1.y = acc[mt][j][3] + acc[mt][j + 4][3];
            *(float2*)(pk + (size_t)r0 * BATCH + n0)       = v0;
            *(float2*)(pk + (size_t)(r0 + 8) * BATCH + n0) = v1;
        }
    }
}

// ---- Kernel 3: reduce k-splits, apply softplus scale + bias -----------------
__global__ void reduce_kernel(const float* __restrict__ log_scale,
                              const float* __restrict__ bias,
                              float* __restrict__ out) {
    int g  = blockIdx.x * blockDim.x + threadIdx.x;
    int o  = g >> 3;
    int bq = g & 7;

    const float4* __restrict__ base = (const float4*)g_partial;
    float4 s = make_float4(0.f, 0.f, 0.f, 0.f);
#pragma unroll
    for (int ky = 0; ky < KSPLIT; ky++) {
        float4 p = base[((size_t)ky * OUT_F + o) * (BATCH / 4) + bq];
        s.x += p.x; s.y += p.y; s.z += p.z; s.w += p.w;
    }

    float ls = log_scale[o];
    float sp = (ls > 20.0f) ? ls : log1pf(expf(ls));   // softplus, overflow-safe
    float sc = fmaxf(sp, 1e-4f);
    float bi = bias[o];

    int b0 = bq << 2;
    out[(size_t)(b0 + 0) * OUT_F + o] = fmaf(sc, s.x, bi);
    out[(size_t)(b0 + 1) * OUT_F + o] = fmaf(sc, s.y, bi);
    out[(size_t)(b0 + 2) * OUT_F + o] = fmaf(sc, s.z, bi);
    out[(size_t)(b0 + 3) * OUT_F + o] = fmaf(sc, s.w, bi);
}

// ---- Launch ------------------------------------------------------------------
extern "C" void kernel_launch(void* const* d_in, const int* in_sizes, int n_in,
                              void* d_out, int out_size) {
    const float* x  = nullptr;
    const int*   W  = nullptr;
    const float* ls = nullptr;
    const float* bi = nullptr;
    for (int i = 0; i < n_in; i++) {
        long long sz = in_sizes[i];
        if (sz == (long long)OUT_F * IN_F)      W = (const int*)d_in[i];
        else if (sz == (long long)BATCH * IN_F) x = (const float*)d_in[i];
        else if (sz == OUT_F) {
            if (!ls) ls = (const float*)d_in[i];
            else     bi = (const float*)d_in[i];
        }
    }
    float* out = (float*)d_out;

    xprep_kernel<<<(BATCH * IN_F / 4) / 256, 256>>>(x);

    dim3 grid(OUT_F / MTILE, KSPLIT);            // (64, 4) = 256 CTAs
    gemm_kernel<<<grid, THREADS>>>(W);

    reduce_kernel<<<(OUT_F * BATCH / 4) / 256, 256>>>(ls, bi, out);
}

// round 7
// speedup vs baseline: 2.1881x; 1.4820x over previous
#include <cuda_runtime.h>
#include <cuda_bf16.h>
#include <cstdint>
#include <cstddef>

#define IN_F   8192
#define OUT_F  8192
#define BATCH  32
#define KSPLIT 8
#define KCHUNK (IN_F / KSPLIT)     // 1024
#define NIT    (KCHUNK / 16)       // 64 k16 steps per CTA
#define MTILE  128                 // rows per CTA (4 warps x 32 rows)
#define THREADS 128
#define NSTEPS (IN_F / 16)         // 512 global k16 steps

// B in fragment order: [step s][n][t] -> {b0,b1} (two u32 = 8 B).
// b0 = bf16x2 X[n][16s+2t .. +1], b1 = bf16x2 X[n][16s+2t+8 .. +9].
// n<32: hi part of x, n>=32: lo residual. Total 1 MB.
__device__ uint32_t g_xbq[(size_t)NSTEPS * 64 * 4 * 2];
__device__ float g_partial[(size_t)KSPLIT * OUT_F * BATCH];      // 8 MB

// ---- helpers -----------------------------------------------------------------
__device__ __forceinline__ uint32_t pack_bf16x2(int lo, int hi) {
    float fl = (float)lo, fh = (float)hi;    // exact for ternary
    uint32_t r;
    asm("cvt.rn.bf16x2.f32 %0, %1, %2;" : "=r"(r) : "f"(fh), "f"(fl));
    return r;
}
__device__ __forceinline__ void mma16816(float* d, uint32_t a0, uint32_t a1,
                                         uint32_t a2, uint32_t a3,
                                         uint32_t b0, uint32_t b1) {
    asm volatile(
        "mma.sync.aligned.m16n8k16.row.col.f32.bf16.bf16.f32 "
        "{%0,%1,%2,%3}, {%4,%5,%6,%7}, {%8,%9}, {%0,%1,%2,%3};"
        : "+f"(d[0]), "+f"(d[1]), "+f"(d[2]), "+f"(d[3])
        : "r"(a0), "r"(a1), "r"(a2), "r"(a3), "r"(b0), "r"(b1));
}
__device__ __forceinline__ uint32_t bf2_u32(__nv_bfloat162 v) {
    uint32_t r; asm("mov.b32 %0, %1;" : "=r"(r) : "r"(*(uint32_t*)&v)); return r;
}

// ---- Kernel 1: x[32][8192] -> hi/lo bf16 in fragment order -------------------
// Thread handles 4 consecutive k (aligned): both bf16x2 pairs land in adjacent
// t-slots (t0, t0+1) of the same (s, half) group.
__global__ void xprep_kernel(const float* __restrict__ x) {
    int gidx = blockIdx.x * blockDim.x + threadIdx.x;   // 65536 threads
    int b  = gidx >> 11;
    int k4 = gidx & 2047;
    int k0 = k4 * 4;
    float4 v = ((const float4*)(x + (size_t)b * IN_F))[k4];

    __nv_bfloat162 hA = __floats2bfloat162_rn(v.x, v.y);
    __nv_bfloat162 hB = __floats2bfloat162_rn(v.z, v.w);
    float lx = v.x - __bfloat162float(hA.x);
    float ly = v.y - __bfloat162float(hA.y);
    float lz = v.z - __bfloat162float(hB.x);
    float lw = v.w - __bfloat162float(hB.y);
    __nv_bfloat162 lA = __floats2bfloat162_rn(lx, ly);
    __nv_bfloat162 lB = __floats2bfloat162_rn(lz, lw);

    int s  = k0 >> 4;
    int q  = k0 & 15;
    int t0 = (q & 7) >> 1;      // 0 or 2
    int h  = q >> 3;            // 0: b0 slot, 1: b1 slot

    // u32 index: ((s*64 + n)*4 + t)*2 + h
    size_t base_hi = ((size_t)(s * 64 + b)       * 4) * 2 + h;
    size_t base_lo = ((size_t)(s * 64 + b + 32)  * 4) * 2 + h;
    g_xbq[base_hi + 2 * (size_t)t0]       = bf2_u32(hA);
    g_xbq[base_hi + 2 * (size_t)(t0 + 1)] = bf2_u32(hB);
    g_xbq[base_lo + 2 * (size_t)t0]       = bf2_u32(lA);
    g_xbq[base_lo + 2 * (size_t)(t0 + 1)] = bf2_u32(lB);
}

// ---- Kernel 2: smem-free HMMA GEMM -------------------------------------------
// grid=(OUT_F/MTILE, KSPLIT)=(64,8)=512 CTAs. Warp owns 32 rows x N=64.
// A and B both prefetched one k16 step ahead; B fragments are single LDG.64.
__global__ void __launch_bounds__(THREADS, 3)
gemm_kernel(const int* __restrict__ W) {
    const int tid  = threadIdx.x;
    const int lane = tid & 31;
    const int warp = tid >> 5;
    const int g    = lane >> 2;        // 0..7
    const int t    = lane & 3;         // 0..3

    const int rowbase = blockIdx.x * MTILE + warp * 32;
    const int kbase   = blockIdx.y * KCHUNK;
    const int sbase   = kbase >> 4;

    const int* __restrict__ p00 = W + (size_t)(rowbase + g     ) * IN_F + kbase + 2 * t;
    const int* __restrict__ p01 = W + (size_t)(rowbase + g +  8) * IN_F + kbase + 2 * t;
    const int* __restrict__ p10 = W + (size_t)(rowbase + g + 16) * IN_F + kbase + 2 * t;
    const int* __restrict__ p11 = W + (size_t)(rowbase + g + 24) * IN_F + kbase + 2 * t;

    // B group pointer for (s, n=g, t): index (s*64+g)*4+t in uint2 units.
    const uint2* __restrict__ xb = ((const uint2*)g_xbq) + ((size_t)sbase * 64 + g) * 4 + t;

    float acc[2][8][4];
#pragma unroll
    for (int mt = 0; mt < 2; mt++)
#pragma unroll
        for (int j = 0; j < 8; j++)
#pragma unroll
            for (int e = 0; e < 4; e++) acc[mt][j][e] = 0.f;

    int2 ca[8], na[8];
    uint2 cb[8], nb[8];

#define LOAD_A(dst, ko)                                              \
    do {                                                             \
        dst[0] = *(const int2*)(p00 + (ko));                         \
        dst[1] = *(const int2*)(p01 + (ko));                         \
        dst[2] = *(const int2*)(p00 + (ko) + 8);                     \
        dst[3] = *(const int2*)(p01 + (ko) + 8);                     \
        dst[4] = *(const int2*)(p10 + (ko));                         \
        dst[5] = *(const int2*)(p11 + (ko));                         \
        dst[6] = *(const int2*)(p10 + (ko) + 8);                     \
        dst[7] = *(const int2*)(p11 + (ko) + 8);                     \
    } while (0)

#define LOAD_B(dst, it_)                                             \
    do {                                                             \
        const uint2* _p = xb + (size_t)(it_) * 256;                  \
        _Pragma("unroll")                                            \
        for (int j = 0; j < 8; j++) dst[j] = _p[j * 32];             \
    } while (0)

    LOAD_A(ca, 0);
    LOAD_B(cb, 0);

#pragma unroll 2
    for (int it = 0; it < NIT; ++it) {
        if (it + 1 < NIT) {
            LOAD_A(na, (it + 1) * 16);
            LOAD_B(nb, it + 1);
        }

        uint32_t A[8];
#pragma unroll
        for (int q = 0; q < 8; q++) A[q] = pack_bf16x2(ca[q].x, ca[q].y);

#pragma unroll
        for (int j = 0; j < 8; j++) {
            mma16816(acc[0][j], A[0], A[1], A[2], A[3], cb[j].x, cb[j].y);
            mma16816(acc[1][j], A[4], A[5], A[6], A[7], cb[j].x, cb[j].y);
        }

#pragma unroll
        for (int q = 0; q < 8; q++) ca[q] = na[q];
#pragma unroll
        for (int j = 0; j < 8; j++) cb[j] = nb[j];
    }

    // Epilogue: combine hi (j<4) + lo (j+4), store f32 partials.
    float* pk = g_partial + (size_t)blockIdx.y * OUT_F * BATCH;
#pragma unroll
    for (int mt = 0; mt < 2; mt++) {
        const int r0 = rowbase + mt * 16 + g;
#pragma unroll
        for (int j = 0; j < 4; j++) {
            const int n0 = 8 * j + 2 * t;
            float2 v0, v1;
            v0.x = acc[mt][j][0] + acc[mt][j + 4][0];
            v0.y = acc[mt][j][1] + acc[mt][j + 4][1];
            v1.x = acc[mt][j][2] + acc[mt][j + 4][2];
            v1.y = acc[mt][j][3] + acc[mt][j + 4][3];
            *(float2*)(pk + (size_t)r0 * BATCH + n0)       = v0;
            *(float2*)(pk + (size_t)(r0 + 8) * BATCH + n0) = v1;
        }
    }
}

// ---- Kernel 3: reduce k-splits, apply softplus scale + bias -----------------
__global__ void reduce_kernel(const float* __restrict__ log_scale,
                              const float* __restrict__ bias,
                              float* __restrict__ out) {
    int g  = blockIdx.x * blockDim.x + threadIdx.x;
    int o  = g >> 3;
    int bq = g & 7;

    const float4* __restrict__ base = (const float4*)g_partial;
    float4 s = make_float4(0.f, 0.f, 0.f, 0.f);
#pragma unroll
    for (int ky = 0; ky < KSPLIT; ky++) {
        float4 p = base[((size_t)ky * OUT_F + o) * (BATCH / 4) + bq];
        s.x += p.x; s.y += p.y; s.z += p.z; s.w += p.w;
    }

    float ls = log_scale[o];
    float sp = (ls > 20.0f) ? ls : log1pf(expf(ls));
    float sc = fmaxf(sp, 1e-4f);
    float bi = bias[o];

    int b0 = bq << 2;
    out[(size_t)(b0 + 0) * OUT_F + o] = fmaf(sc, s.x, bi);
    out[(size_t)(b0 + 1) * OUT_F + o] = fmaf(sc, s.y, bi);
    out[(size_t)(b0 + 2) * OUT_F + o] = fmaf(sc, s.z, bi);
    out[(size_t)(b0 + 3) * OUT_F + o] = fmaf(sc, s.w, bi);
}

// ---- Launch ------------------------------------------------------------------
extern "C" void kernel_launch(void* const* d_in, const int* in_sizes, int n_in,
                              void* d_out, int out_size) {
    const float* x  = nullptr;
    const int*   W  = nullptr;
    const float* ls = nullptr;
    const float* bi = nullptr;
    for (int i = 0; i < n_in; i++) {
        long long sz = in_sizes[i];
        if (sz == (long long)OUT_F * IN_F)      W = (const int*)d_in[i];
        else if (sz == (long long)BATCH * IN_F) x = (const float*)d_in[i];
        else if (sz == OUT_F) {
            if (!ls) ls = (const float*)d_in[i];
            else     bi = (const float*)d_in[i];
        }
    }
    float* out = (float*)d_out;

    xprep_kernel<<<(BATCH * IN_F / 4) / 256, 256>>>(x);

    dim3 grid(OUT_F / MTILE, KSPLIT);            // (64, 8) = 512 CTAs
    gemm_kernel<<<grid, THREADS>>>(W);

    reduce_kernel<<<(OUT_F * BATCH / 4) / 256, 256>>>(ls, bi, out);
}

// round 8
// speedup vs baseline: 2.3452x; 1.0718x over previous
#include <cuda_runtime.h>
#include <cuda_bf16.h>
#include <cstdint>
#include <cstddef>

#define IN_F   8192
#define OUT_F  8192
#define BATCH  32
#define KSPLIT 32
#define KCHUNK (IN_F / KSPLIT)     // 256
#define NIT    (KCHUNK / 16)       // 16 k16 steps per CTA
#define MTILE  128                 // rows per CTA (4 warps x 32 rows)
#define THREADS 128
#define NSTEPS (IN_F / 16)         // 512 global k16 steps

// B in fragment order: [step s][n][t] -> {b0,b1} (uint2, 8 B).
// b0 = bf16x2 X[n][16s+2t .. +1], b1 = bf16x2 X[n][16s+2t+8 .. +9].
// n<32: hi bf16 of x, n>=32: lo residual. Total 1 MB.
__device__ uint32_t g_xbq[(size_t)NSTEPS * 64 * 4 * 2];
__device__ float g_partial[(size_t)KSPLIT * OUT_F * BATCH];      // 32 MB

// ---- helpers -----------------------------------------------------------------
__device__ __forceinline__ uint32_t pack_bf16x2(int lo, int hi) {
    float fl = (float)lo, fh = (float)hi;    // exact for ternary
    uint32_t r;
    asm("cvt.rn.bf16x2.f32 %0, %1, %2;" : "=r"(r) : "f"(fh), "f"(fl));
    return r;
}
__device__ __forceinline__ void mma16816(float* d, uint32_t a0, uint32_t a1,
                                         uint32_t a2, uint32_t a3,
                                         uint32_t b0, uint32_t b1) {
    asm volatile(
        "mma.sync.aligned.m16n8k16.row.col.f32.bf16.bf16.f32 "
        "{%0,%1,%2,%3}, {%4,%5,%6,%7}, {%8,%9}, {%0,%1,%2,%3};"
        : "+f"(d[0]), "+f"(d[1]), "+f"(d[2]), "+f"(d[3])
        : "r"(a0), "r"(a1), "r"(a2), "r"(a3), "r"(b0), "r"(b1));
}
__device__ __forceinline__ uint32_t bf2_u32(__nv_bfloat162 v) {
    uint32_t r; asm("mov.b32 %0, %1;" : "=r"(r) : "r"(*(uint32_t*)&v)); return r;
}

// ---- Kernel 1: x[32][8192] -> hi/lo bf16 in fragment order -------------------
__global__ void xprep_kernel(const float* __restrict__ x) {
    int gidx = blockIdx.x * blockDim.x + threadIdx.x;   // 65536 threads
    int b  = gidx >> 11;
    int k4 = gidx & 2047;
    int k0 = k4 * 4;
    float4 v = ((const float4*)(x + (size_t)b * IN_F))[k4];

    __nv_bfloat162 hA = __floats2bfloat162_rn(v.x, v.y);
    __nv_bfloat162 hB = __floats2bfloat162_rn(v.z, v.w);
    float lx = v.x - __bfloat162float(hA.x);
    float ly = v.y - __bfloat162float(hA.y);
    float lz = v.z - __bfloat162float(hB.x);
    float lw = v.w - __bfloat162float(hB.y);
    __nv_bfloat162 lA = __floats2bfloat162_rn(lx, ly);
    __nv_bfloat162 lB = __floats2bfloat162_rn(lz, lw);

    int s  = k0 >> 4;
    int q  = k0 & 15;
    int t0 = (q & 7) >> 1;      // 0 or 2
    int h  = q >> 3;            // 0: b0 slot, 1: b1 slot

    size_t base_hi = ((size_t)(s * 64 + b)      * 4) * 2 + h;
    size_t base_lo = ((size_t)(s * 64 + b + 32) * 4) * 2 + h;
    g_xbq[base_hi + 2 * (size_t)t0]       = bf2_u32(hA);
    g_xbq[base_hi + 2 * (size_t)(t0 + 1)] = bf2_u32(hB);
    g_xbq[base_lo + 2 * (size_t)t0]       = bf2_u32(lA);
    g_xbq[base_lo + 2 * (size_t)(t0 + 1)] = bf2_u32(lB);
}

// ---- Kernel 2: HMMA GEMM, B staged in smem -----------------------------------
// grid=(OUT_F/MTILE, KSPLIT)=(64,32)=2048 CTAs, occ 4. Warp owns 32 rows x N=64.
// A (DRAM stream) prefetched one step ahead in regs; B read via LDS.64.
__global__ void __launch_bounds__(THREADS, 4)
gemm_kernel(const int* __restrict__ W) {
    __shared__ uint2 sB[NIT * 256];                    // 32 KB

    const int tid  = threadIdx.x;
    const int lane = tid & 31;
    const int warp = tid >> 5;
    const int g    = lane >> 2;        // 0..7
    const int t    = lane & 3;         // 0..3

    const int rowbase = blockIdx.x * MTILE + warp * 32;
    const int kbase   = blockIdx.y * KCHUNK;
    const int sbase   = kbase >> 4;

    // Stage this CTA's whole B slice (contiguous 32 KB of g_xbq), coalesced.
    {
        const uint4* __restrict__ src =
            (const uint4*)(((const uint2*)g_xbq) + (size_t)sbase * 256);
        uint4* dst = (uint4*)sB;
#pragma unroll
        for (int i = tid; i < NIT * 128; i += THREADS) dst[i] = src[i];
    }

    // Single W base pointer; row offsets become SASS LDG immediates.
    const int* __restrict__ pA = W + (size_t)(rowbase + g) * IN_F + kbase + 2 * t;

    float acc[2][8][4];
#pragma unroll
    for (int mt = 0; mt < 2; mt++)
#pragma unroll
        for (int j = 0; j < 8; j++)
#pragma unroll
            for (int e = 0; e < 4; e++) acc[mt][j][e] = 0.f;

    int2 ca[8], na[8];

#define LOAD_A(dst, ko)                                                       \
    do {                                                                      \
        dst[0] = *(const int2*)(pA + (ko));                                   \
        dst[1] = *(const int2*)(pA + (size_t)8  * IN_F + (ko));               \
        dst[2] = *(const int2*)(pA + (ko) + 8);                               \
        dst[3] = *(const int2*)(pA + (size_t)8  * IN_F + (ko) + 8);           \
        dst[4] = *(const int2*)(pA + (size_t)16 * IN_F + (ko));               \
        dst[5] = *(const int2*)(pA + (size_t)24 * IN_F + (ko));               \
        dst[6] = *(const int2*)(pA + (size_t)16 * IN_F + (ko) + 8);           \
        dst[7] = *(const int2*)(pA + (size_t)24 * IN_F + (ko) + 8);           \
    } while (0)

    LOAD_A(ca, 0);
    __syncthreads();

#pragma unroll 2
    for (int it = 0; it < NIT; ++it) {
        if (it + 1 < NIT) LOAD_A(na, (it + 1) * 16);

        uint32_t A[8];
#pragma unroll
        for (int q = 0; q < 8; q++) A[q] = pack_bf16x2(ca[q].x, ca[q].y);

        const uint2* __restrict__ bp = sB + it * 256 + g * 4 + t;
#pragma unroll
        for (int j = 0; j < 8; j++) {
            uint2 bv = bp[j * 32];                     // LDS.64, conflict-free
            mma16816(acc[0][j], A[0], A[1], A[2], A[3], bv.x, bv.y);
            mma16816(acc[1][j], A[4], A[5], A[6], A[7], bv.x, bv.y);
        }

#pragma unroll
        for (int q = 0; q < 8; q++) ca[q] = na[q];
    }

    // Epilogue: combine hi (j<4) + lo (j+4), store f32 partials.
    float* pk = g_partial + (size_t)blockIdx.y * OUT_F * BATCH;
#pragma unroll
    for (int mt = 0; mt < 2; mt++) {
        const int r0 = rowbase + mt * 16 + g;
#pragma unroll
        for (int j = 0; j < 4; j++) {
            const int n0 = 8 * j + 2 * t;
            float2 v0, v1;
            v0.x = acc[mt][j][0] + acc[mt][j + 4][0];
            v0.y = acc[mt][j][1] + acc[mt][j + 4][1];
            v1.x = acc[mt][j][2] + acc[mt][j + 4][2];
            v1.y = acc[mt][j][3] + acc[mt][j + 4][3];
            *(float2*)(pk + (size_t)r0 * BATCH + n0)       = v0;
            *(float2*)(pk + (size_t)(r0 + 8) * BATCH + n0) = v1;
        }
    }
}

// ---- Kernel 3: reduce k-splits, apply softplus scale + bias -----------------
__global__ void reduce_kernel(const float* __restrict__ log_scale,
                              const float* __restrict__ bias,
                              float* __restrict__ out) {
    int g  = blockIdx.x * blockDim.x + threadIdx.x;
    int o  = g >> 3;
    int bq = g & 7;

    const float4* __restrict__ base = (const float4*)g_partial;
    float4 s = make_float4(0.f, 0.f, 0.f, 0.f);
#pragma unroll
    for (int ky = 0; ky < KSPLIT; ky++) {
        float4 p = base[((size_t)ky * OUT_F + o) * (BATCH / 4) + bq];
        s.x += p.x; s.y += p.y; s.z += p.z; s.w += p.w;
    }

    float ls = log_scale[o];
    float sp = (ls > 20.0f) ? ls : log1pf(expf(ls));
    float sc = fmaxf(sp, 1e-4f);
    float bi = bias[o];

    int b0 = bq << 2;
    out[(size_t)(b0 + 0) * OUT_F + o] = fmaf(sc, s.x, bi);
    out[(size_t)(b0 + 1) * OUT_F + o] = fmaf(sc, s.y, bi);
    out[(size_t)(b0 + 2) * OUT_F + o] = fmaf(sc, s.z, bi);
    out[(size_t)(b0 + 3) * OUT_F + o] = fmaf(sc, s.w, bi);
}

// ---- Launch ------------------------------------------------------------------
extern "C" void kernel_launch(void* const* d_in, const int* in_sizes, int n_in,
                              void* d_out, int out_size) {
    const float* x  = nullptr;
    const int*   W  = nullptr;
    const float* ls = nullptr;
    const float* bi = nullptr;
    for (int i = 0; i < n_in; i++) {
        long long sz = in_sizes[i];
        if (sz == (long long)OUT_F * IN_F)      W = (const int*)d_in[i];
        else if (sz == (long long)BATCH * IN_F) x = (const float*)d_in[i];
        else if (sz == OUT_F) {
            if (!ls) ls = (const float*)d_in[i];
            else     bi = (const float*)d_in[i];
        }
    }
    float* out = (float*)d_out;

    xprep_kernel<<<(BATCH * IN_F / 4) / 128, 128>>>(x);

    dim3 grid(OUT_F / MTILE, KSPLIT);            // (64, 32) = 2048 CTAs
    gemm_kernel<<<grid, THREADS>>>(W);

    reduce_kernel<<<(OUT_F * BATCH / 4) / 256, 256>>>(ls, bi, out);
}